// round 15
// baseline (speedup 1.0000x reference)
#include <cuda_runtime.h>
#include <cuda_fp16.h>
#include <cstdint>

// Problem constants
#define BZ 4
#define SEQ 2048
#define DM 1024
#define NH 16
#define HD 64
#define M_TOT 8192
#define N_TOT 3072

// Scratch (fp16)
__device__ __half g_Qh[BZ*NH*SEQ*HD];
__device__ __half g_Kh[BZ*NH*SEQ*HD];
__device__ __half g_Vh[BZ*NH*SEQ*HD];
__device__ __half g_Xh[M_TOT*DM];
__device__ __half g_Wh[(size_t)DM*N_TOT];   // W fp16, NATIVE [k][n] layout

// ---------------------------------------------------------------------------
// helpers
// ---------------------------------------------------------------------------
__device__ __forceinline__ void mma16(float* c, const uint32_t* a, uint32_t b0, uint32_t b1){
    asm volatile("mma.sync.aligned.m16n8k16.row.col.f32.f16.f16.f32 "
        "{%0,%1,%2,%3}, {%4,%5,%6,%7}, {%8,%9}, {%0,%1,%2,%3};"
        : "+f"(c[0]), "+f"(c[1]), "+f"(c[2]), "+f"(c[3])
        : "r"(a[0]), "r"(a[1]), "r"(a[2]), "r"(a[3]), "r"(b0), "r"(b1));
}
__device__ __forceinline__ void ldsm4(uint32_t* r, uint32_t addr){
    asm volatile("ldmatrix.sync.aligned.m8n8.x4.shared.b16 {%0,%1,%2,%3}, [%4];"
        : "=r"(r[0]), "=r"(r[1]), "=r"(r[2]), "=r"(r[3]) : "r"(addr));
}
__device__ __forceinline__ void ldsm4t(uint32_t* r, uint32_t addr){
    asm volatile("ldmatrix.sync.aligned.m8n8.x4.trans.shared.b16 {%0,%1,%2,%3}, [%4];"
        : "=r"(r[0]), "=r"(r[1]), "=r"(r[2]), "=r"(r[3]) : "r"(addr));
}
__device__ __forceinline__ uint32_t pack2(float lo, float hi){
    uint32_t r; asm("cvt.rn.f16x2.f32 %0, %1, %2;" : "=r"(r) : "f"(hi), "f"(lo)); return r;
}
__device__ __forceinline__ uint32_t smem_u32(const void* p){
    uint32_t a;
    asm("{ .reg .u64 t; cvta.to.shared.u64 t, %1; cvt.u32.u64 %0, t; }" : "=r"(a) : "l"(p));
    return a;
}
__device__ __forceinline__ void cp16(uint32_t dst, const void* src){
    asm volatile("cp.async.cg.shared.global [%0], [%1], 16;" :: "r"(dst), "l"(src));
}
#define CP_COMMIT() asm volatile("cp.async.commit_group;" ::: "memory")
#define CP_WAIT(n)  asm volatile("cp.async.wait_group %0;" :: "n"(n) : "memory")

// ---------------------------------------------------------------------------
// Prepass: fused elementwise fp32 -> fp16, 2x float4 per thread per iter.
// ---------------------------------------------------------------------------
__global__ __launch_bounds__(256) void cvt_all(const float* __restrict__ x,
                                               const float* __restrict__ W)
{
    const size_t NX = (size_t)M_TOT * DM / 4;
    const size_t NT = NX + (size_t)DM * N_TOT / 4;
    const size_t gid = (size_t)blockIdx.x * blockDim.x + threadIdx.x;
    const size_t stride = (size_t)gridDim.x * blockDim.x;
    for (size_t i0 = gid * 2; i0 < NT; i0 += stride * 2) {
        #pragma unroll
        for (int u = 0; u < 2; u++) {
            size_t i = i0 + u;
            if (i >= NT) break;
            if (i < NX) {
                float4 v = ((const float4*)x)[i];
                __half2* o = (__half2*)(g_Xh + i * 4);
                o[0] = __floats2half2_rn(v.x, v.y);
                o[1] = __floats2half2_rn(v.z, v.w);
            } else {
                size_t j = i - NX;
                float4 v = ((const float4*)W)[j];
                __half2* o = (__half2*)(g_Wh + j * 4);
                o[0] = __floats2half2_rn(v.x, v.y);
                o[1] = __floats2half2_rn(v.z, v.w);
            }
        }
    }
}

// ---------------------------------------------------------------------------
// Kernel 1: QKV GEMM, fp16 mma, BK=64, 3-stage cp.async. (unchanged: at floor)
// CTA tile 256x96, 8 warps (4M x 2N), warp tile 64x48. B [k][n] via ldsm4t.
// ---------------------------------------------------------------------------
#define ASTR 72
#define BSTR 104
#define TN_G 96
#define SA_H (256*ASTR)
#define SB_H (64*BSTR)
#define SA_B (SA_H*2)
#define SB_B (SB_H*2)
#define NKB  (DM/64)
#define NSTG 3

__global__ __launch_bounds__(256, 1) void qkv_gemm(const float* __restrict__ bias)
{
    extern __shared__ __half smh[];
    __half* sA = smh;
    __half* sB = smh + NSTG * SA_H;
    const uint32_t uA = smem_u32(sA);
    const uint32_t uB = smem_u32(sB);

    const int tid  = threadIdx.x;
    const int wid  = tid >> 5;
    const int lane = tid & 31;
    const int g = lane >> 2, t = lane & 3;
    const int wrow = wid & 3;
    const int wcol = wid >> 2;
    const int bm = blockIdx.y, bn = blockIdx.x;

    const __half* Ab = g_Xh + (size_t)(bm * 256) * DM;
    const __half* Bb = g_Wh + (size_t)bn * TN_G;

    int arow[8], acol[8];
    #pragma unroll
    for (int l = 0; l < 8; l++) {
        int idx = tid + l * 256;
        arow[l] = idx >> 3;
        acol[l] = (idx & 7) * 8;
    }
    int brow[3], bcol[3];
    #pragma unroll
    for (int l = 0; l < 3; l++) {
        int idx = tid + l * 256;
        brow[l] = idx / 12;
        bcol[l] = (idx % 12) * 8;
    }

    auto issue = [&](int slot, int k0) {
        uint32_t pa = uA + slot * SA_B;
        uint32_t pb = uB + slot * SB_B;
        #pragma unroll
        for (int l = 0; l < 8; l++)
            cp16(pa + (arow[l] * ASTR + acol[l]) * 2, Ab + (size_t)arow[l] * DM + k0 + acol[l]);
        #pragma unroll
        for (int l = 0; l < 3; l++)
            cp16(pb + (brow[l] * BSTR + bcol[l]) * 2, Bb + (size_t)(k0 + brow[l]) * N_TOT + bcol[l]);
    };

    float acc[4][6][4];
    #pragma unroll
    for (int mt = 0; mt < 4; mt++)
        #pragma unroll
        for (int nt = 0; nt < 6; nt++)
            #pragma unroll
            for (int e = 0; e < 4; e++) acc[mt][nt][e] = 0.f;

    issue(0, 0);   CP_COMMIT();
    issue(1, 64);  CP_COMMIT();
    CP_WAIT(1);
    __syncthreads();

    const uint32_t aBase = uA + (wrow * 64 + (lane & 15)) * (ASTR * 2) + ((lane & 16) ? 16 : 0);
    const uint32_t bBase = uB + ((lane & 7) + ((lane & 8) ? 8 : 0)) * (BSTR * 2)
                         + ((lane & 16) ? 16 : 0) + wcol * 48 * 2;

    int slot = 0;
    #pragma unroll 1
    for (int kb = 0; kb < NKB; kb++) {
        const uint32_t aS = aBase + slot * SA_B;
        const uint32_t bS = bBase + slot * SB_B;

        uint32_t af[2][4][4], bf[2][3][4];
        #pragma unroll
        for (int kt = 0; kt < 2; kt++) {
            #pragma unroll
            for (int mt = 0; mt < 4; mt++)
                ldsm4(af[kt][mt], aS + mt * 16 * (ASTR * 2) + kt * 32);
            #pragma unroll
            for (int ntp = 0; ntp < 3; ntp++)
                ldsm4t(bf[kt][ntp], bS + kt * 16 * (BSTR * 2) + ntp * 32);
        }

        if (kb + 2 < NKB) {
            int ns = slot + 2; if (ns >= NSTG) ns -= NSTG;
            issue(ns, (kb + 2) * 64);
            CP_COMMIT();
        }

        #pragma unroll
        for (int kt = 0; kt < 2; kt++)
            #pragma unroll
            for (int mt = 0; mt < 4; mt++)
                #pragma unroll
                for (int nt = 0; nt < 6; nt++)
                    mma16(acc[mt][nt], af[kt][mt],
                          bf[kt][nt >> 1][(nt & 1) * 2], bf[kt][nt >> 1][(nt & 1) * 2 + 1]);

        #pragma unroll
        for (int kt = 0; kt < 2; kt++) {
            #pragma unroll
            for (int mt = 0; mt < 4; mt++)
                ldsm4(af[kt][mt], aS + mt * 16 * (ASTR * 2) + (kt + 2) * 32);
            #pragma unroll
            for (int ntp = 0; ntp < 3; ntp++)
                ldsm4t(bf[kt][ntp], bS + (kt + 2) * 16 * (BSTR * 2) + ntp * 32);
        }
        #pragma unroll
        for (int kt = 0; kt < 2; kt++)
            #pragma unroll
            for (int mt = 0; mt < 4; mt++)
                #pragma unroll
                for (int nt = 0; nt < 6; nt++)
                    mma16(acc[mt][nt], af[kt][mt],
                          bf[kt][nt >> 1][(nt & 1) * 2], bf[kt][nt >> 1][(nt & 1) * 2 + 1]);

        if (kb + 2 < NKB)      { CP_WAIT(1); }
        else if (kb + 1 < NKB) { CP_WAIT(0); }
        __syncthreads();
        if (++slot == NSTG) slot = 0;
    }

    #pragma unroll
    for (int nt = 0; nt < 6; nt++) {
        int n0 = bn * TN_G + wcol * 48 + nt * 8 + 2 * t;
        float bx = __ldg(&bias[n0]), by = __ldg(&bias[n0 + 1]);
        int h = n0 / 192;
        int r = n0 - h * 192;
        __half* dst = (r < 64) ? g_Qh : ((r < 128) ? g_Kh : g_Vh);
        float scl = (r < 64) ? 0.125f : 1.f;
        #pragma unroll
        for (int mt = 0; mt < 4; mt++) {
            #pragma unroll
            for (int half_ = 0; half_ < 2; half_++) {
                int m  = bm * 256 + wrow * 64 + mt * 16 + g + half_ * 8;
                int b_ = m >> 11;
                int s_ = m & 2047;
                size_t o = ((((size_t)b_ * NH + h) * SEQ) + s_) * HD + (r & 63);
                *(__half2*)(dst + o) = __floats2half2_rn((acc[mt][nt][half_ * 2]     + bx) * scl,
                                                         (acc[mt][nt][half_ * 2 + 1] + by) * scl);
            }
        }
    }
}

// ---------------------------------------------------------------------------
// Kernel 2: causal flash attention, fp16 mma + ldmatrix, register-resident P.
// CTAQ=128: 4 warps x 32 q-rows, 128 threads, 2 CTAs/SM.
// 3-stage KV ring: end-of-iter WAIT(1) — needed tile had a full iteration
// to arrive; just-issued tile legally remains in flight.
// ---------------------------------------------------------------------------
#define QSTR 72
#define KSTR 72
#define KV_B (64*KSTR*2)
#define CTAQ 128
#define NTHR 128
#define KSTG 3
#define L2E 1.44269504f

__global__ __launch_bounds__(NTHR, 2) void attn_fa(float* __restrict__ out)
{
    extern __shared__ __half smh[];
    __half* Qs = smh;
    __half* Ks = Qs + CTAQ * QSTR;            // [3][64][KSTR]
    __half* Vs = Ks + KSTG * 64 * KSTR;       // [3][64][KSTR]
    const uint32_t uQ = smem_u32(Qs);
    const uint32_t uK = smem_u32(Ks);
    const uint32_t uV = smem_u32(Vs);

    const int tid  = threadIdx.x;
    const int wid  = tid >> 5;
    const int lane = tid & 31;
    const int g = lane >> 2, t = lane & 3;
    const int qt = gridDim.x - 1 - blockIdx.x;    // big-work CTAs first
    const int h = blockIdx.y, b = blockIdx.z;
    const int wb = wid * 32;
    const int qbase = qt * CTAQ;
    const int row0 = qbase + wb + g;

    const size_t hb = (((size_t)b * NH + h) * SEQ) * HD;
    const int nkb = (qt + 1) * (CTAQ / 64);

    int kvrow[4], kvcol[4];
    #pragma unroll
    for (int i = 0; i < 4; i++) {
        int idx = tid + i * NTHR;
        kvrow[i] = idx >> 3;
        kvcol[i] = (idx & 7) * 8;
    }
    auto issueKV = [&](int kb, int slot) {
        const __half* ks = g_Kh + hb + (size_t)kb * 64 * HD;
        const __half* vs = g_Vh + hb + (size_t)kb * 64 * HD;
        #pragma unroll
        for (int i = 0; i < 4; i++) {
            cp16(uK + slot * KV_B + (kvrow[i] * KSTR + kvcol[i]) * 2, ks + kvrow[i] * HD + kvcol[i]);
            cp16(uV + slot * KV_B + (kvrow[i] * KSTR + kvcol[i]) * 2, vs + kvrow[i] * HD + kvcol[i]);
        }
    };

    // Prologue: {Q + KV0} group, {KV1} group. WAIT(1) -> Q+KV0 complete.
    {
        const __half* qs = g_Qh + hb + (size_t)qbase * HD;
        #pragma unroll
        for (int i = 0; i < 8; i++) {
            int idx = tid + i * NTHR;
            int r = idx >> 3, c = (idx & 7) * 8;
            cp16(uQ + (r * QSTR + c) * 2, qs + r * HD + c);
        }
    }
    issueKV(0, 0);
    CP_COMMIT();
    if (nkb > 1) { issueKV(1, 1); CP_COMMIT(); CP_WAIT(1); }
    else         { CP_WAIT(0); }
    __syncthreads();

    uint32_t aq[2][4][4];
    {
        const uint32_t qb = uQ + (wb + (lane & 15)) * (QSTR * 2) + ((lane & 16) ? 16 : 0);
        #pragma unroll
        for (int mt = 0; mt < 2; mt++)
            #pragma unroll
            for (int kt = 0; kt < 4; kt++)
                ldsm4(aq[mt][kt], qb + mt * 16 * (QSTR * 2) + kt * 32);
    }

    float o[2][8][4];
    #pragma unroll
    for (int mt = 0; mt < 2; mt++)
        #pragma unroll
        for (int nt = 0; nt < 8; nt++)
            #pragma unroll
            for (int e = 0; e < 4; e++) o[mt][nt][e] = 0.f;
    float m00 = -1e30f, m01 = -1e30f, m10 = -1e30f, m11 = -1e30f;
    float l00 = 0.f, l01 = 0.f, l10 = 0.f, l11 = 0.f;

    const uint32_t kfOff = ((lane & 7) + ((lane & 16) ? 8 : 0)) * (KSTR * 2) + ((lane & 8) ? 16 : 0);
    const uint32_t vfOff = ((lane & 7) + ((lane & 8) ? 8 : 0)) * (KSTR * 2) + ((lane & 16) ? 16 : 0);

    int slot = 0;
    #pragma unroll 1
    for (int kb = 0; kb < nkb; kb++) {
        // slot's data (tile kb) is complete and visible here.

        // Issue tile kb+2 into slot (kb+2)%3 — last read by iter kb-1,
        // certified finished by the barrier we already passed.
        if (kb + 2 < nkb) {
            int ns = slot + 2; if (ns >= KSTG) ns -= KSTG;
            issueKV(kb + 2, ns);
            CP_COMMIT();
        }

        if (kb * 64 <= qbase + wb + 31) {
            float s[2][8][4];
            #pragma unroll
            for (int mt = 0; mt < 2; mt++)
                #pragma unroll
                for (int nt = 0; nt < 8; nt++)
                    #pragma unroll
                    for (int e = 0; e < 4; e++) s[mt][nt][e] = 0.f;

            const uint32_t kbase_ = uK + slot * KV_B + kfOff;
            #pragma unroll
            for (int kt = 0; kt < 4; kt++) {
                uint32_t kf[4][4];
                #pragma unroll
                for (int ntp = 0; ntp < 4; ntp++)
                    ldsm4(kf[ntp], kbase_ + ntp * 16 * (KSTR * 2) + kt * 32);
                #pragma unroll
                for (int nt = 0; nt < 8; nt++) {
                    uint32_t b0 = kf[nt >> 1][(nt & 1) * 2], b1 = kf[nt >> 1][(nt & 1) * 2 + 1];
                    mma16(s[0][nt], aq[0][kt], b0, b1);
                    mma16(s[1][nt], aq[1][kt], b0, b1);
                }
            }

            if (kb * 64 + 63 > qbase + wb) {
                #pragma unroll
                for (int nt = 0; nt < 8; nt++) {
                    int col = kb * 64 + nt * 8 + 2 * t;
                    if (col     > row0)      s[0][nt][0] = -1e30f;
                    if (col + 1 > row0)      s[0][nt][1] = -1e30f;
                    if (col     > row0 + 8)  s[0][nt][2] = -1e30f;
                    if (col + 1 > row0 + 8)  s[0][nt][3] = -1e30f;
                    if (col     > row0 + 16) s[1][nt][0] = -1e30f;
                    if (col + 1 > row0 + 16) s[1][nt][1] = -1e30f;
                    if (col     > row0 + 24) s[1][nt][2] = -1e30f;
                    if (col + 1 > row0 + 24) s[1][nt][3] = -1e30f;
                }
            }

            float b00 = -1e30f, b01 = -1e30f, b10 = -1e30f, b11 = -1e30f;
            #pragma unroll
            for (int nt = 0; nt < 8; nt++) {
                b00 = fmaxf(b00, fmaxf(s[0][nt][0], s[0][nt][1]));
                b01 = fmaxf(b01, fmaxf(s[0][nt][2], s[0][nt][3]));
                b10 = fmaxf(b10, fmaxf(s[1][nt][0], s[1][nt][1]));
                b11 = fmaxf(b11, fmaxf(s[1][nt][2], s[1][nt][3]));
            }
            #pragma unroll
            for (int d = 1; d <= 2; d <<= 1) {
                b00 = fmaxf(b00, __shfl_xor_sync(0xffffffffu, b00, d));
                b01 = fmaxf(b01, __shfl_xor_sync(0xffffffffu, b01, d));
                b10 = fmaxf(b10, __shfl_xor_sync(0xffffffffu, b10, d));
                b11 = fmaxf(b11, __shfl_xor_sync(0xffffffffu, b11, d));
            }
            float n00 = fmaxf(m00, b00), n01 = fmaxf(m01, b01);
            float n10 = fmaxf(m10, b10), n11 = fmaxf(m11, b11);
            float c00 = exp2f((m00 - n00) * L2E), c01 = exp2f((m01 - n01) * L2E);
            float c10 = exp2f((m10 - n10) * L2E), c11 = exp2f((m11 - n11) * L2E);

            uint32_t pc[2][8][2];
            float s00 = 0.f, s01 = 0.f, s10 = 0.f, s11 = 0.f;
            #pragma unroll
            for (int nt = 0; nt < 8; nt++) {
                float p0 = exp2f((s[0][nt][0] - n00) * L2E);
                float p1 = exp2f((s[0][nt][1] - n00) * L2E);
                float p2 = exp2f((s[0][nt][2] - n01) * L2E);
                float p3 = exp2f((s[0][nt][3] - n01) * L2E);
                float q0 = exp2f((s[1][nt][0] - n10) * L2E);
                float q1 = exp2f((s[1][nt][1] - n10) * L2E);
                float q2 = exp2f((s[1][nt][2] - n11) * L2E);
                float q3 = exp2f((s[1][nt][3] - n11) * L2E);
                s00 += p0 + p1; s01 += p2 + p3;
                s10 += q0 + q1; s11 += q2 + q3;
                pc[0][nt][0] = pack2(p0, p1);
                pc[0][nt][1] = pack2(p2, p3);
                pc[1][nt][0] = pack2(q0, q1);
                pc[1][nt][1] = pack2(q2, q3);
            }
            #pragma unroll
            for (int d = 1; d <= 2; d <<= 1) {
                s00 += __shfl_xor_sync(0xffffffffu, s00, d);
                s01 += __shfl_xor_sync(0xffffffffu, s01, d);
                s10 += __shfl_xor_sync(0xffffffffu, s10, d);
                s11 += __shfl_xor_sync(0xffffffffu, s11, d);
            }
            l00 = l00 * c00 + s00; l01 = l01 * c01 + s01;
            l10 = l10 * c10 + s10; l11 = l11 * c11 + s11;
            m00 = n00; m01 = n01; m10 = n10; m11 = n11;

            #pragma unroll
            for (int nt = 0; nt < 8; nt++) {
                o[0][nt][0] *= c00; o[0][nt][1] *= c00;
                o[0][nt][2] *= c01; o[0][nt][3] *= c01;
                o[1][nt][0] *= c10; o[1][nt][1] *= c10;
                o[1][nt][2] *= c11; o[1][nt][3] *= c11;
            }

            const uint32_t vbase_ = uV + slot * KV_B + vfOff;
            #pragma unroll
            for (int kt = 0; kt < 4; kt++) {
                uint32_t vf[4][4];
                #pragma unroll
                for (int ntp = 0; ntp < 4; ntp++)
                    ldsm4t(vf[ntp], vbase_ + kt * 16 * (KSTR * 2) + ntp * 32);
                uint32_t ap0[4] = {pc[0][2*kt][0], pc[0][2*kt][1], pc[0][2*kt+1][0], pc[0][2*kt+1][1]};
                uint32_t ap1[4] = {pc[1][2*kt][0], pc[1][2*kt][1], pc[1][2*kt+1][0], pc[1][2*kt+1][1]};
                #pragma unroll
                for (int nt = 0; nt < 8; nt++) {
                    uint32_t b0 = vf[nt >> 1][(nt & 1) * 2], b1 = vf[nt >> 1][(nt & 1) * 2 + 1];
                    mma16(o[0][nt], ap0, b0, b1);
                    mma16(o[1][nt], ap1, b0, b1);
                }
            }
        }

        // End of iteration: ensure tile kb+1 (needed next) is complete, then
        // one barrier for visibility + read-completion of current slot.
        if (kb + 1 < nkb) {
            if (kb + 2 < nkb) { CP_WAIT(1); }   // kb+2 may stay in flight
            else              { CP_WAIT(0); }   // nothing else outstanding
            __syncthreads();
        }
        if (++slot == KSTG) slot = 0;
    }

    const float i00 = 1.f / l00, i01 = 1.f / l01;
    const float i10 = 1.f / l10, i11 = 1.f / l11;
    float* w00 = out + ((size_t)b * SEQ + row0) * DM + h * HD + 2 * t;
    float* w01 = out + ((size_t)b * SEQ + row0 + 8) * DM + h * HD + 2 * t;
    float* w10 = out + ((size_t)b * SEQ + row0 + 16) * DM + h * HD + 2 * t;
    float* w11 = out + ((size_t)b * SEQ + row0 + 24) * DM + h * HD + 2 * t;
    #pragma unroll
    for (int nt = 0; nt < 8; nt++) {
        *(float2*)(w00 + nt * 8) = make_float2(o[0][nt][0] * i00, o[0][nt][1] * i00);
        *(float2*)(w01 + nt * 8) = make_float2(o[0][nt][2] * i01, o[0][nt][3] * i01);
        *(float2*)(w10 + nt * 8) = make_float2(o[1][nt][0] * i10, o[1][nt][1] * i10);
        *(float2*)(w11 + nt * 8) = make_float2(o[1][nt][2] * i11, o[1][nt][3] * i11);
    }
}

// ---------------------------------------------------------------------------
extern "C" void kernel_launch(void* const* d_in, const int* in_sizes, int n_in,
                              void* d_out, int out_size)
{
    (void)in_sizes; (void)n_in; (void)out_size;
    const float* x    = (const float*)d_in[0];
    const float* Wqkv = (const float*)d_in[1];
    const float* bqkv = (const float*)d_in[2];
    float* out = (float*)d_out;

    cvt_all<<<1184, 256>>>(x, Wqkv);

    const int gemm_smem = NSTG * (SA_B + SB_B);                    // 150528 B
    cudaFuncSetAttribute(qkv_gemm, cudaFuncAttributeMaxDynamicSharedMemorySize, gemm_smem);
    dim3 ggrid(N_TOT / TN_G, M_TOT / 256);                         // (32, 32)
    qkv_gemm<<<ggrid, 256, gemm_smem>>>(bqkv);

    const int attn_smem = (CTAQ * QSTR + 2 * KSTG * 64 * KSTR) * 2; // 73728 B
    cudaFuncSetAttribute(attn_fa, cudaFuncAttributeMaxDynamicSharedMemorySize, attn_smem);
    dim3 agrid(SEQ / CTAQ, NH, BZ);                                 // (16, 16, 4)
    attn_fa<<<agrid, NTHR, attn_smem>>>(out);
}

// round 16
// speedup vs baseline: 1.0147x; 1.0147x over previous
#include <cuda_runtime.h>
#include <cuda_fp16.h>
#include <cstdint>

// Problem constants
#define BZ 4
#define SEQ 2048
#define DM 1024
#define NH 16
#define HD 64
#define M_TOT 8192
#define N_TOT 3072

// Scratch (fp16)
__device__ __half g_Qh[BZ*NH*SEQ*HD];
__device__ __half g_Kh[BZ*NH*SEQ*HD];
__device__ __half g_Vh[BZ*NH*SEQ*HD];
__device__ __half g_Xh[M_TOT*DM];
__device__ __half g_Wh[(size_t)DM*N_TOT];   // W fp16, NATIVE [k][n] layout

// ---------------------------------------------------------------------------
// helpers
// ---------------------------------------------------------------------------
__device__ __forceinline__ void mma16(float* c, const uint32_t* a, uint32_t b0, uint32_t b1){
    asm volatile("mma.sync.aligned.m16n8k16.row.col.f32.f16.f16.f32 "
        "{%0,%1,%2,%3}, {%4,%5,%6,%7}, {%8,%9}, {%0,%1,%2,%3};"
        : "+f"(c[0]), "+f"(c[1]), "+f"(c[2]), "+f"(c[3])
        : "r"(a[0]), "r"(a[1]), "r"(a[2]), "r"(a[3]), "r"(b0), "r"(b1));
}
__device__ __forceinline__ void ldsm4(uint32_t* r, uint32_t addr){
    asm volatile("ldmatrix.sync.aligned.m8n8.x4.shared.b16 {%0,%1,%2,%3}, [%4];"
        : "=r"(r[0]), "=r"(r[1]), "=r"(r[2]), "=r"(r[3]) : "r"(addr));
}
__device__ __forceinline__ void ldsm4t(uint32_t* r, uint32_t addr){
    asm volatile("ldmatrix.sync.aligned.m8n8.x4.trans.shared.b16 {%0,%1,%2,%3}, [%4];"
        : "=r"(r[0]), "=r"(r[1]), "=r"(r[2]), "=r"(r[3]) : "r"(addr));
}
__device__ __forceinline__ uint32_t pack2(float lo, float hi){
    uint32_t r; asm("cvt.rn.f16x2.f32 %0, %1, %2;" : "=r"(r) : "f"(hi), "f"(lo)); return r;
}
__device__ __forceinline__ uint32_t smem_u32(const void* p){
    uint32_t a;
    asm("{ .reg .u64 t; cvta.to.shared.u64 t, %1; cvt.u32.u64 %0, t; }" : "=r"(a) : "l"(p));
    return a;
}
__device__ __forceinline__ void cp16(uint32_t dst, const void* src){
    asm volatile("cp.async.cg.shared.global [%0], [%1], 16;" :: "r"(dst), "l"(src));
}
#define CP_COMMIT() asm volatile("cp.async.commit_group;" ::: "memory")
#define CP_WAIT(n)  asm volatile("cp.async.wait_group %0;" :: "n"(n) : "memory")

// ---------------------------------------------------------------------------
// Prepass: fused elementwise fp32 -> fp16 (round-14 simple form, optimal).
// ---------------------------------------------------------------------------
__global__ __launch_bounds__(256) void cvt_all(const float* __restrict__ x,
                                               const float* __restrict__ W)
{
    const size_t NX = (size_t)M_TOT * DM / 4;
    const size_t NT = NX + (size_t)DM * N_TOT / 4;
    const size_t gid = (size_t)blockIdx.x * blockDim.x + threadIdx.x;
    const size_t stride = (size_t)gridDim.x * blockDim.x;
    for (size_t i = gid; i < NT; i += stride) {
        if (i < NX) {
            float4 v = ((const float4*)x)[i];
            __half2* o = (__half2*)(g_Xh + i * 4);
            o[0] = __floats2half2_rn(v.x, v.y);
            o[1] = __floats2half2_rn(v.z, v.w);
        } else {
            size_t j = i - NX;
            float4 v = ((const float4*)W)[j];
            __half2* o = (__half2*)(g_Wh + j * 4);
            o[0] = __floats2half2_rn(v.x, v.y);
            o[1] = __floats2half2_rn(v.z, v.w);
        }
    }
}

// ---------------------------------------------------------------------------
// Kernel 1: QKV GEMM, fp16 mma, BK=64, 3-stage cp.async. (at HMMA issue floor)
// CTA tile 256x96, 8 warps (4M x 2N), warp tile 64x48. B [k][n] via ldsm4t.
// ---------------------------------------------------------------------------
#define ASTR 72
#define BSTR 104
#define TN_G 96
#define SA_H (256*ASTR)
#define SB_H (64*BSTR)
#define SA_B (SA_H*2)
#define SB_B (SB_H*2)
#define NKB  (DM/64)
#define NSTG 3

__global__ __launch_bounds__(256, 1) void qkv_gemm(const float* __restrict__ bias)
{
    extern __shared__ __half smh[];
    __half* sA = smh;
    __half* sB = smh + NSTG * SA_H;
    const uint32_t uA = smem_u32(sA);
    const uint32_t uB = smem_u32(sB);

    const int tid  = threadIdx.x;
    const int wid  = tid >> 5;
    const int lane = tid & 31;
    const int g = lane >> 2, t = lane & 3;
    const int wrow = wid & 3;
    const int wcol = wid >> 2;
    const int bm = blockIdx.y, bn = blockIdx.x;

    const __half* Ab = g_Xh + (size_t)(bm * 256) * DM;
    const __half* Bb = g_Wh + (size_t)bn * TN_G;

    int arow[8], acol[8];
    #pragma unroll
    for (int l = 0; l < 8; l++) {
        int idx = tid + l * 256;
        arow[l] = idx >> 3;
        acol[l] = (idx & 7) * 8;
    }
    int brow[3], bcol[3];
    #pragma unroll
    for (int l = 0; l < 3; l++) {
        int idx = tid + l * 256;
        brow[l] = idx / 12;
        bcol[l] = (idx % 12) * 8;
    }

    auto issue = [&](int slot, int k0) {
        uint32_t pa = uA + slot * SA_B;
        uint32_t pb = uB + slot * SB_B;
        #pragma unroll
        for (int l = 0; l < 8; l++)
            cp16(pa + (arow[l] * ASTR + acol[l]) * 2, Ab + (size_t)arow[l] * DM + k0 + acol[l]);
        #pragma unroll
        for (int l = 0; l < 3; l++)
            cp16(pb + (brow[l] * BSTR + bcol[l]) * 2, Bb + (size_t)(k0 + brow[l]) * N_TOT + bcol[l]);
    };

    float acc[4][6][4];
    #pragma unroll
    for (int mt = 0; mt < 4; mt++)
        #pragma unroll
        for (int nt = 0; nt < 6; nt++)
            #pragma unroll
            for (int e = 0; e < 4; e++) acc[mt][nt][e] = 0.f;

    issue(0, 0);   CP_COMMIT();
    issue(1, 64);  CP_COMMIT();
    CP_WAIT(1);
    __syncthreads();

    const uint32_t aBase = uA + (wrow * 64 + (lane & 15)) * (ASTR * 2) + ((lane & 16) ? 16 : 0);
    const uint32_t bBase = uB + ((lane & 7) + ((lane & 8) ? 8 : 0)) * (BSTR * 2)
                         + ((lane & 16) ? 16 : 0) + wcol * 48 * 2;

    int slot = 0;
    #pragma unroll 1
    for (int kb = 0; kb < NKB; kb++) {
        const uint32_t aS = aBase + slot * SA_B;
        const uint32_t bS = bBase + slot * SB_B;

        uint32_t af[2][4][4], bf[2][3][4];
        #pragma unroll
        for (int kt = 0; kt < 2; kt++) {
            #pragma unroll
            for (int mt = 0; mt < 4; mt++)
                ldsm4(af[kt][mt], aS + mt * 16 * (ASTR * 2) + kt * 32);
            #pragma unroll
            for (int ntp = 0; ntp < 3; ntp++)
                ldsm4t(bf[kt][ntp], bS + kt * 16 * (BSTR * 2) + ntp * 32);
        }

        if (kb + 2 < NKB) {
            int ns = slot + 2; if (ns >= NSTG) ns -= NSTG;
            issue(ns, (kb + 2) * 64);
            CP_COMMIT();
        }

        #pragma unroll
        for (int kt = 0; kt < 2; kt++)
            #pragma unroll
            for (int mt = 0; mt < 4; mt++)
                #pragma unroll
                for (int nt = 0; nt < 6; nt++)
                    mma16(acc[mt][nt], af[kt][mt],
                          bf[kt][nt >> 1][(nt & 1) * 2], bf[kt][nt >> 1][(nt & 1) * 2 + 1]);

        #pragma unroll
        for (int kt = 0; kt < 2; kt++) {
            #pragma unroll
            for (int mt = 0; mt < 4; mt++)
                ldsm4(af[kt][mt], aS + mt * 16 * (ASTR * 2) + (kt + 2) * 32);
            #pragma unroll
            for (int ntp = 0; ntp < 3; ntp++)
                ldsm4t(bf[kt][ntp], bS + (kt + 2) * 16 * (BSTR * 2) + ntp * 32);
        }
        #pragma unroll
        for (int kt = 0; kt < 2; kt++)
            #pragma unroll
            for (int mt = 0; mt < 4; mt++)
                #pragma unroll
                for (int nt = 0; nt < 6; nt++)
                    mma16(acc[mt][nt], af[kt][mt],
                          bf[kt][nt >> 1][(nt & 1) * 2], bf[kt][nt >> 1][(nt & 1) * 2 + 1]);

        if (kb + 2 < NKB)      { CP_WAIT(1); }
        else if (kb + 1 < NKB) { CP_WAIT(0); }
        __syncthreads();
        if (++slot == NSTG) slot = 0;
    }

    #pragma unroll
    for (int nt = 0; nt < 6; nt++) {
        int n0 = bn * TN_G + wcol * 48 + nt * 8 + 2 * t;
        float bx = __ldg(&bias[n0]), by = __ldg(&bias[n0 + 1]);
        int h = n0 / 192;
        int r = n0 - h * 192;
        __half* dst = (r < 64) ? g_Qh : ((r < 128) ? g_Kh : g_Vh);
        float scl = (r < 64) ? 0.125f : 1.f;
        #pragma unroll
        for (int mt = 0; mt < 4; mt++) {
            #pragma unroll
            for (int half_ = 0; half_ < 2; half_++) {
                int m  = bm * 256 + wrow * 64 + mt * 16 + g + half_ * 8;
                int b_ = m >> 11;
                int s_ = m & 2047;
                size_t o = ((((size_t)b_ * NH + h) * SEQ) + s_) * HD + (r & 63);
                *(__half2*)(dst + o) = __floats2half2_rn((acc[mt][nt][half_ * 2]     + bx) * scl,
                                                         (acc[mt][nt][half_ * 2 + 1] + by) * scl);
            }
        }
    }
}

// ---------------------------------------------------------------------------
// Kernel 2: causal flash attention, fp16 mma + ldmatrix, register-resident P.
// CTAQ=128: 4 warps x 32 q-rows, 128 threads, 2 CTAs/SM, 3-stage KV ring.
// l (row-sum) kept as per-lane partials; cross-lane reduced ONCE in epilogue.
// ---------------------------------------------------------------------------
#define QSTR 72
#define KSTR 72
#define KV_B (64*KSTR*2)
#define CTAQ 128
#define NTHR 128
#define KSTG 3
#define L2E 1.44269504f

__global__ __launch_bounds__(NTHR, 2) void attn_fa(float* __restrict__ out)
{
    extern __shared__ __half smh[];
    __half* Qs = smh;
    __half* Ks = Qs + CTAQ * QSTR;            // [3][64][KSTR]
    __half* Vs = Ks + KSTG * 64 * KSTR;       // [3][64][KSTR]
    const uint32_t uQ = smem_u32(Qs);
    const uint32_t uK = smem_u32(Ks);
    const uint32_t uV = smem_u32(Vs);

    const int tid  = threadIdx.x;
    const int wid  = tid >> 5;
    const int lane = tid & 31;
    const int g = lane >> 2, t = lane & 3;
    const int qt = gridDim.x - 1 - blockIdx.x;    // big-work CTAs first
    const int h = blockIdx.y, b = blockIdx.z;
    const int wb = wid * 32;
    const int qbase = qt * CTAQ;
    const int row0 = qbase + wb + g;

    const size_t hb = (((size_t)b * NH + h) * SEQ) * HD;
    const int nkb = (qt + 1) * (CTAQ / 64);

    int kvrow[4], kvcol[4];
    #pragma unroll
    for (int i = 0; i < 4; i++) {
        int idx = tid + i * NTHR;
        kvrow[i] = idx >> 3;
        kvcol[i] = (idx & 7) * 8;
    }
    auto issueKV = [&](int kb, int slot) {
        const __half* ks = g_Kh + hb + (size_t)kb * 64 * HD;
        const __half* vs = g_Vh + hb + (size_t)kb * 64 * HD;
        #pragma unroll
        for (int i = 0; i < 4; i++) {
            cp16(uK + slot * KV_B + (kvrow[i] * KSTR + kvcol[i]) * 2, ks + kvrow[i] * HD + kvcol[i]);
            cp16(uV + slot * KV_B + (kvrow[i] * KSTR + kvcol[i]) * 2, vs + kvrow[i] * HD + kvcol[i]);
        }
    };

    // Prologue: {Q + KV0} group, {KV1} group. WAIT(1) -> Q+KV0 complete.
    {
        const __half* qs = g_Qh + hb + (size_t)qbase * HD;
        #pragma unroll
        for (int i = 0; i < 8; i++) {
            int idx = tid + i * NTHR;
            int r = idx >> 3, c = (idx & 7) * 8;
            cp16(uQ + (r * QSTR + c) * 2, qs + r * HD + c);
        }
    }
    issueKV(0, 0);
    CP_COMMIT();
    if (nkb > 1) { issueKV(1, 1); CP_COMMIT(); CP_WAIT(1); }
    else         { CP_WAIT(0); }
    __syncthreads();

    uint32_t aq[2][4][4];
    {
        const uint32_t qb = uQ + (wb + (lane & 15)) * (QSTR * 2) + ((lane & 16) ? 16 : 0);
        #pragma unroll
        for (int mt = 0; mt < 2; mt++)
            #pragma unroll
            for (int kt = 0; kt < 4; kt++)
                ldsm4(aq[mt][kt], qb + mt * 16 * (QSTR * 2) + kt * 32);
    }

    float o[2][8][4];
    #pragma unroll
    for (int mt = 0; mt < 2; mt++)
        #pragma unroll
        for (int nt = 0; nt < 8; nt++)
            #pragma unroll
            for (int e = 0; e < 4; e++) o[mt][nt][e] = 0.f;
    float m00 = -1e30f, m01 = -1e30f, m10 = -1e30f, m11 = -1e30f;
    float l00 = 0.f, l01 = 0.f, l10 = 0.f, l11 = 0.f;   // per-lane partials

    const uint32_t kfOff = ((lane & 7) + ((lane & 16) ? 8 : 0)) * (KSTR * 2) + ((lane & 8) ? 16 : 0);
    const uint32_t vfOff = ((lane & 7) + ((lane & 8) ? 8 : 0)) * (KSTR * 2) + ((lane & 16) ? 16 : 0);

    int slot = 0;
    #pragma unroll 1
    for (int kb = 0; kb < nkb; kb++) {
        // slot's data (tile kb) is complete and visible here.
        if (kb + 2 < nkb) {
            int ns = slot + 2; if (ns >= KSTG) ns -= KSTG;
            issueKV(kb + 2, ns);
            CP_COMMIT();
        }

        if (kb * 64 <= qbase + wb + 31) {
            float s[2][8][4];
            #pragma unroll
            for (int mt = 0; mt < 2; mt++)
                #pragma unroll
                for (int nt = 0; nt < 8; nt++)
                    #pragma unroll
                    for (int e = 0; e < 4; e++) s[mt][nt][e] = 0.f;

            const uint32_t kbase_ = uK + slot * KV_B + kfOff;
            #pragma unroll
            for (int kt = 0; kt < 4; kt++) {
                uint32_t kf[4][4];
                #pragma unroll
                for (int ntp = 0; ntp < 4; ntp++)
                    ldsm4(kf[ntp], kbase_ + ntp * 16 * (KSTR * 2) + kt * 32);
                #pragma unroll
                for (int nt = 0; nt < 8; nt++) {
                    uint32_t b0 = kf[nt >> 1][(nt & 1) * 2], b1 = kf[nt >> 1][(nt & 1) * 2 + 1];
                    mma16(s[0][nt], aq[0][kt], b0, b1);
                    mma16(s[1][nt], aq[1][kt], b0, b1);
                }
            }

            if (kb * 64 + 63 > qbase + wb) {
                #pragma unroll
                for (int nt = 0; nt < 8; nt++) {
                    int col = kb * 64 + nt * 8 + 2 * t;
                    if (col     > row0)      s[0][nt][0] = -1e30f;
                    if (col + 1 > row0)      s[0][nt][1] = -1e30f;
                    if (col     > row0 + 8)  s[0][nt][2] = -1e30f;
                    if (col + 1 > row0 + 8)  s[0][nt][3] = -1e30f;
                    if (col     > row0 + 16) s[1][nt][0] = -1e30f;
                    if (col + 1 > row0 + 16) s[1][nt][1] = -1e30f;
                    if (col     > row0 + 24) s[1][nt][2] = -1e30f;
                    if (col + 1 > row0 + 24) s[1][nt][3] = -1e30f;
                }
            }

            // row max (needs cross-lane reduce before exp)
            float b00 = -1e30f, b01 = -1e30f, b10 = -1e30f, b11 = -1e30f;
            #pragma unroll
            for (int nt = 0; nt < 8; nt++) {
                b00 = fmaxf(b00, fmaxf(s[0][nt][0], s[0][nt][1]));
                b01 = fmaxf(b01, fmaxf(s[0][nt][2], s[0][nt][3]));
                b10 = fmaxf(b10, fmaxf(s[1][nt][0], s[1][nt][1]));
                b11 = fmaxf(b11, fmaxf(s[1][nt][2], s[1][nt][3]));
            }
            #pragma unroll
            for (int d = 1; d <= 2; d <<= 1) {
                b00 = fmaxf(b00, __shfl_xor_sync(0xffffffffu, b00, d));
                b01 = fmaxf(b01, __shfl_xor_sync(0xffffffffu, b01, d));
                b10 = fmaxf(b10, __shfl_xor_sync(0xffffffffu, b10, d));
                b11 = fmaxf(b11, __shfl_xor_sync(0xffffffffu, b11, d));
            }
            float n00 = fmaxf(m00, b00), n01 = fmaxf(m01, b01);
            float n10 = fmaxf(m10, b10), n11 = fmaxf(m11, b11);
            float c00 = exp2f((m00 - n00) * L2E), c01 = exp2f((m01 - n01) * L2E);
            float c10 = exp2f((m10 - n10) * L2E), c11 = exp2f((m11 - n11) * L2E);

            uint32_t pc[2][8][2];
            float s00 = 0.f, s01 = 0.f, s10 = 0.f, s11 = 0.f;
            #pragma unroll
            for (int nt = 0; nt < 8; nt++) {
                float p0 = exp2f((s[0][nt][0] - n00) * L2E);
                float p1 = exp2f((s[0][nt][1] - n00) * L2E);
                float p2 = exp2f((s[0][nt][2] - n01) * L2E);
                float p3 = exp2f((s[0][nt][3] - n01) * L2E);
                float q0 = exp2f((s[1][nt][0] - n10) * L2E);
                float q1 = exp2f((s[1][nt][1] - n10) * L2E);
                float q2 = exp2f((s[1][nt][2] - n11) * L2E);
                float q3 = exp2f((s[1][nt][3] - n11) * L2E);
                s00 += p0 + p1; s01 += p2 + p3;
                s10 += q0 + q1; s11 += q2 + q3;
                pc[0][nt][0] = pack2(p0, p1);
                pc[0][nt][1] = pack2(p2, p3);
                pc[1][nt][0] = pack2(q0, q1);
                pc[1][nt][1] = pack2(q2, q3);
            }
            // per-lane partial only — cross-lane reduce deferred to epilogue
            l00 = l00 * c00 + s00; l01 = l01 * c01 + s01;
            l10 = l10 * c10 + s10; l11 = l11 * c11 + s11;
            m00 = n00; m01 = n01; m10 = n10; m11 = n11;

            #pragma unroll
            for (int nt = 0; nt < 8; nt++) {
                o[0][nt][0] *= c00; o[0][nt][1] *= c00;
                o[0][nt][2] *= c01; o[0][nt][3] *= c01;
                o[1][nt][0] *= c10; o[1][nt][1] *= c10;
                o[1][nt][2] *= c11; o[1][nt][3] *= c11;
            }

            const uint32_t vbase_ = uV + slot * KV_B + vfOff;
            #pragma unroll
            for (int kt = 0; kt < 4; kt++) {
                uint32_t vf[4][4];
                #pragma unroll
                for (int ntp = 0; ntp < 4; ntp++)
                    ldsm4t(vf[ntp], vbase_ + kt * 16 * (KSTR * 2) + ntp * 32);
                uint32_t ap0[4] = {pc[0][2*kt][0], pc[0][2*kt][1], pc[0][2*kt+1][0], pc[0][2*kt+1][1]};
                uint32_t ap1[4] = {pc[1][2*kt][0], pc[1][2*kt][1], pc[1][2*kt+1][0], pc[1][2*kt+1][1]};
                #pragma unroll
                for (int nt = 0; nt < 8; nt++) {
                    uint32_t b0 = vf[nt >> 1][(nt & 1) * 2], b1 = vf[nt >> 1][(nt & 1) * 2 + 1];
                    mma16(o[0][nt], ap0, b0, b1);
                    mma16(o[1][nt], ap1, b0, b1);
                }
            }
        }

        if (kb + 1 < nkb) {
            if (kb + 2 < nkb) { CP_WAIT(1); }
            else              { CP_WAIT(0); }
            __syncthreads();
        }
        if (++slot == KSTG) slot = 0;
    }

    // Epilogue: single cross-lane reduction of l partials (quad lanes t=0..3).
    #pragma unroll
    for (int d = 1; d <= 2; d <<= 1) {
        l00 += __shfl_xor_sync(0xffffffffu, l00, d);
        l01 += __shfl_xor_sync(0xffffffffu, l01, d);
        l10 += __shfl_xor_sync(0xffffffffu, l10, d);
        l11 += __shfl_xor_sync(0xffffffffu, l11, d);
    }

    const float i00 = 1.f / l00, i01 = 1.f / l01;
    const float i10 = 1.f / l10, i11 = 1.f / l11;
    float* w00 = out + ((size_t)b * SEQ + row0) * DM + h * HD + 2 * t;
    float* w01 = out + ((size_t)b * SEQ + row0 + 8) * DM + h * HD + 2 * t;
    float* w10 = out + ((size_t)b * SEQ + row0 + 16) * DM + h * HD + 2 * t;
    float* w11 = out + ((size_t)b * SEQ + row0 + 24) * DM + h * HD + 2 * t;
    #pragma unroll
    for (int nt = 0; nt < 8; nt++) {
        *(float2*)(w00 + nt * 8) = make_float2(o[0][nt][0] * i00, o[0][nt][1] * i00);
        *(float2*)(w01 + nt * 8) = make_float2(o[0][nt][2] * i01, o[0][nt][3] * i01);
        *(float2*)(w10 + nt * 8) = make_float2(o[1][nt][0] * i10, o[1][nt][1] * i10);
        *(float2*)(w11 + nt * 8) = make_float2(o[1][nt][2] * i11, o[1][nt][3] * i11);
    }
}

// ---------------------------------------------------------------------------
extern "C" void kernel_launch(void* const* d_in, const int* in_sizes, int n_in,
                              void* d_out, int out_size)
{
    (void)in_sizes; (void)n_in; (void)out_size;
    const float* x    = (const float*)d_in[0];
    const float* Wqkv = (const float*)d_in[1];
    const float* bqkv = (const float*)d_in[2];
    float* out = (float*)d_out;

    cvt_all<<<1184, 256>>>(x, Wqkv);

    const int gemm_smem = NSTG * (SA_B + SB_B);                    // 150528 B
    cudaFuncSetAttribute(qkv_gemm, cudaFuncAttributeMaxDynamicSharedMemorySize, gemm_smem);
    dim3 ggrid(N_TOT / TN_G, M_TOT / 256);                         // (32, 32)
    qkv_gemm<<<ggrid, 256, gemm_smem>>>(bqkv);

    const int attn_smem = (CTAQ * QSTR + 2 * KSTG * 64 * KSTR) * 2; // 73728 B
    cudaFuncSetAttribute(attn_fa, cudaFuncAttributeMaxDynamicSharedMemorySize, attn_smem);
    dim3 agrid(SEQ / CTAQ, NH, BZ);                                 // (16, 16, 4)
    attn_fa<<<agrid, NTHR, attn_smem>>>(out);
}